// round 12
// baseline (speedup 1.0000x reference)
#include <cuda_runtime.h>
#include <cuda_fp16.h>
#include <cstdint>

// ---------------- problem constants (fixed-shape problem) ----------------
#define NNODES 20000
#define NEDGES 320000
#define ETOT   (NEDGES + NNODES)
#define NGRAPH 64
#define FIN    64
#define HID    64
#define NHEAD  8
#define GFEAT  16
#define NCLS   10
#define NEG    0.2f
#define D1     (NHEAD * HID)   // 512

// ---------------- device scratch (static, no allocation) ----------------
__device__ __half g_xl1h[(size_t)NNODES * D1];   // gathered per edge -> fp16
__device__ float  g_xr1 [(size_t)NNODES * D1];
__device__ float  g_h1  [(size_t)NNODES * D1];
__device__ __half g_xl2h[(size_t)NNODES * HID];  // gathered per edge -> fp16
__device__ float  g_xr2 [(size_t)NNODES * HID];
__device__ int    g_deg[NNODES];
__device__ int    g_cur[NNODES];
__device__ int    g_row[NNODES + 1];
__device__ int    g_src[ETOT];
__device__ float  g_pool[NGRAPH * HID];
__device__ float  g_cnt[NGRAPH];

// ---------------- init scratch counters ----------------
__global__ void zero_kernel() {
    int i = blockIdx.x * blockDim.x + threadIdx.x;
    if (i < NNODES) { g_deg[i] = 0; g_cur[i] = 0; }
    if (i < NGRAPH * HID) g_pool[i] = 0.f;
    if (i < NGRAPH) g_cnt[i] = 0.f;
}

// ---------------- CSR build: count -> scan -> scatter ----------------
__global__ void count_kernel(const int* __restrict__ ei) {
    int base = (blockIdx.x * blockDim.x + threadIdx.x) * 4;
    #pragma unroll
    for (int i = 0; i < 4; i++) {
        int e = base + i;
        if (e < ETOT) {
            int d = (e < NEDGES) ? ei[NEDGES + e] : (e - NEDGES);
            atomicAdd(&g_deg[d], 1);
        }
    }
}

// single-block exclusive scan over NNODES (warp-shuffle based, 20 iters)
__global__ void scan_kernel() {
    __shared__ int warpsum[32];
    __shared__ int carry_sh;
    int tid = threadIdx.x;
    int lane = tid & 31, wid = tid >> 5;
    if (tid == 0) { carry_sh = 0; g_row[0] = 0; }
    __syncthreads();
    for (int base = 0; base < NNODES; base += 1024) {
        int i = base + tid;
        int v = (i < NNODES) ? g_deg[i] : 0;
        #pragma unroll
        for (int off = 1; off < 32; off <<= 1) {
            int t = __shfl_up_sync(0xffffffffu, v, off);
            if (lane >= off) v += t;
        }
        if (lane == 31) warpsum[wid] = v;
        __syncthreads();
        if (wid == 0) {
            int w = warpsum[lane];
            #pragma unroll
            for (int off = 1; off < 32; off <<= 1) {
                int t = __shfl_up_sync(0xffffffffu, w, off);
                if (lane >= off) w += t;
            }
            warpsum[lane] = w;
        }
        __syncthreads();
        int add = carry_sh + (wid > 0 ? warpsum[wid - 1] : 0);
        int incl = v + add;
        if (i < NNODES) g_row[i + 1] = incl;
        __syncthreads();             // everyone has read carry_sh
        if (tid == 1023) carry_sh = incl;
        __syncthreads();
    }
}

__global__ void scatter_kernel(const int* __restrict__ ei) {
    int base = (blockIdx.x * blockDim.x + threadIdx.x) * 4;
    #pragma unroll
    for (int i = 0; i < 4; i++) {
        int e = base + i;
        if (e < ETOT) {
            int s, d;
            if (e < NEDGES) { s = ei[e]; d = ei[NEDGES + e]; }
            else            { s = d = e - NEDGES; }
            int pos = atomicAdd(&g_cur[d], 1);
            g_src[g_row[d] + pos] = s;
        }
    }
}

// ---------------- tf32 tensor-core GEMM, virtual-M fused L/R projection ----------------
// C[N, 2*Mreal] = A[N,K] @ [Wl | Wr] + [bl | br]
// Left half (xl) stored fp16 (gathered per edge later); right half (xr) fp32.
__device__ __forceinline__ uint32_t f2tf(float f) {
    uint32_t r; asm("cvt.rna.tf32.f32 %0, %1;" : "=r"(r) : "f"(f)); return r;
}
__device__ __forceinline__ void mma_tf32(float c[4],
    uint32_t a0, uint32_t a1, uint32_t a2, uint32_t a3, uint32_t b0, uint32_t b1)
{
    asm volatile(
        "mma.sync.aligned.m16n8k8.row.col.f32.tf32.tf32.f32 "
        "{%0,%1,%2,%3}, {%4,%5,%6,%7}, {%8,%9}, {%0,%1,%2,%3};"
        : "+f"(c[0]), "+f"(c[1]), "+f"(c[2]), "+f"(c[3])
        : "r"(a0), "r"(a1), "r"(a2), "r"(a3), "r"(b0), "r"(b1));
}

__global__ __launch_bounds__(256, 2) void gemm_tc_kernel(
    int layer, const float* __restrict__ Aext,
    const float* __restrict__ Wl, const float* __restrict__ bl,
    const float* __restrict__ Wr, const float* __restrict__ br)
{
    __shared__ uint32_t As[128][36];
    __shared__ uint32_t Bs[32][136];

    int K, Mreal;
    const float* A;
    if (layer == 1) { K = FIN; Mreal = D1;  A = Aext; }
    else            { K = D1;  Mreal = HID; A = g_h1; }

    int tid = threadIdx.x;
    int wid = tid >> 5, lane = tid & 31;
    int wm = (wid >> 2) * 64;
    int wn = (wid & 3) * 32;
    int grp = lane >> 2, tig = lane & 3;
    int n0 = blockIdx.x * 128;

    float acc[4][4][4];
    #pragma unroll
    for (int i = 0; i < 4; i++)
        #pragma unroll
        for (int j = 0; j < 4; j++)
            #pragma unroll
            for (int r = 0; r < 4; r++) acc[i][j][r] = 0.f;

    for (int k0 = 0; k0 < K; k0 += 32) {
        #pragma unroll
        for (int i = 0; i < 4; i++) {
            int lin = tid + i * 256;
            int r = lin >> 3, kq = (lin & 7) * 4;
            int gr = n0 + r;
            float4 v = make_float4(0.f, 0.f, 0.f, 0.f);
            if (gr < NNODES) v = *(const float4*)&A[(size_t)gr * K + k0 + kq];
            As[r][kq + 0] = f2tf(v.x); As[r][kq + 1] = f2tf(v.y);
            As[r][kq + 2] = f2tf(v.z); As[r][kq + 3] = f2tf(v.w);
        }
        #pragma unroll
        for (int i = 0; i < 4; i++) {
            int lin = tid + i * 256;
            int k = lin >> 5, nq = (lin & 31) * 4;
            int vc = blockIdx.y * 128 + nq;
            bool bleft = vc < Mreal;
            int col = bleft ? vc : vc - Mreal;
            const float* W = bleft ? Wl : Wr;
            float4 v = *(const float4*)&W[(size_t)(k0 + k) * Mreal + col];
            Bs[k][nq + 0] = f2tf(v.x); Bs[k][nq + 1] = f2tf(v.y);
            Bs[k][nq + 2] = f2tf(v.z); Bs[k][nq + 3] = f2tf(v.w);
        }
        __syncthreads();

        #pragma unroll
        for (int ks = 0; ks < 4; ks++) {
            int kk = ks * 8;
            uint32_t af[4][4];
            #pragma unroll
            for (int mf = 0; mf < 4; mf++) {
                int row = wm + mf * 16 + grp;
                af[mf][0] = As[row][kk + tig];
                af[mf][1] = As[row + 8][kk + tig];
                af[mf][2] = As[row][kk + tig + 4];
                af[mf][3] = As[row + 8][kk + tig + 4];
            }
            #pragma unroll
            for (int nf = 0; nf < 4; nf++) {
                int col = wn + nf * 8 + grp;
                uint32_t b0 = Bs[kk + tig][col];
                uint32_t b1 = Bs[kk + tig + 4][col];
                #pragma unroll
                for (int mf = 0; mf < 4; mf++)
                    mma_tf32(acc[mf][nf], af[mf][0], af[mf][1], af[mf][2], af[mf][3], b0, b1);
            }
        }
        __syncthreads();
    }

    // epilogue: bias + store. xl (left) -> fp16, xr (right) -> fp32.
    #pragma unroll
    for (int nf = 0; nf < 4; nf++) {
        int vc = blockIdx.y * 128 + wn + nf * 8 + tig * 2;
        bool left = vc < Mreal;
        int col = left ? vc : vc - Mreal;
        const float* bm = left ? bl : br;
        float2 bv = *(const float2*)&bm[col];
        if (left) {
            __half* C = (layer == 1) ? g_xl1h : g_xl2h;
            #pragma unroll
            for (int mf = 0; mf < 4; mf++) {
                int r0 = n0 + wm + mf * 16 + grp;
                if (r0 < NNODES)
                    *(__half2*)&C[(size_t)r0 * Mreal + col] =
                        __floats2half2_rn(acc[mf][nf][0] + bv.x, acc[mf][nf][1] + bv.y);
                int r1 = r0 + 8;
                if (r1 < NNODES)
                    *(__half2*)&C[(size_t)r1 * Mreal + col] =
                        __floats2half2_rn(acc[mf][nf][2] + bv.x, acc[mf][nf][3] + bv.y);
            }
        } else {
            float* C = (layer == 1) ? g_xr1 : g_xr2;
            #pragma unroll
            for (int mf = 0; mf < 4; mf++) {
                int r0 = n0 + wm + mf * 16 + grp;
                if (r0 < NNODES)
                    *(float2*)&C[(size_t)r0 * Mreal + col] =
                        make_float2(acc[mf][nf][0] + bv.x, acc[mf][nf][1] + bv.y);
                int r1 = r0 + 8;
                if (r1 < NNODES)
                    *(float2*)&C[(size_t)r1 * Mreal + col] =
                        make_float2(acc[mf][nf][2] + bv.x, acc[mf][nf][3] + bv.y);
            }
        }
    }
}

// ---------------- GATv2 layer 1: 2 warps/node, 4 heads/warp, 8 ch/lane ----------------
// xl1 gathered as fp16 (one 16B load per lane per edge)
__global__ __launch_bounds__(256) void edge1_kernel(
    const float* __restrict__ att, const float* __restrict__ bias)
{
    int warp = threadIdx.x >> 5;
    int n = blockIdx.x * 4 + (warp >> 1);
    int wp = warp & 1;
    int lane = threadIdx.x & 31;
    int coff = wp * 256 + (lane >> 3) * 64 + (lane & 7) * 8;

    float4 av0 = *(const float4*)&att[coff];
    float4 av1 = *(const float4*)&att[coff + 4];
    float4 xr0 = *(const float4*)&g_xr1[(size_t)n * D1 + coff];
    float4 xr1 = *(const float4*)&g_xr1[(size_t)n * D1 + coff + 4];

    int e0 = g_row[n], e1 = g_row[n + 1];
    float m = -3.4e38f, s = 0.f;
    float acc[8];
    #pragma unroll
    for (int i = 0; i < 8; i++) acc[i] = 0.f;

    const uint4* xlv = (const uint4*)g_xl1h;   // 8 halves = 16B per lane slice
    int c8 = coff >> 3;                        // uint4 index within row (row = 64 uint4)

    int src = g_src[e0];
    uint4 a = xlv[(size_t)src * 64 + c8];

    for (int e = e0; e < e1; e++) {
        uint4 hv = a;
        if (e + 1 < e1) {
            int ns = g_src[e + 1];
            a = xlv[(size_t)ns * 64 + c8];
        }
        float2 f0 = __half22float2(*(__half2*)&hv.x);
        float2 f1 = __half22float2(*(__half2*)&hv.y);
        float2 f2 = __half22float2(*(__half2*)&hv.z);
        float2 f3 = __half22float2(*(__half2*)&hv.w);

        float p;
        {
            float v, l;
            v = f0.x + xr0.x; l = fmaxf(v, NEG * v); p  = l * av0.x;
            v = f0.y + xr0.y; l = fmaxf(v, NEG * v); p += l * av0.y;
            v = f1.x + xr0.z; l = fmaxf(v, NEG * v); p += l * av0.z;
            v = f1.y + xr0.w; l = fmaxf(v, NEG * v); p += l * av0.w;
            v = f2.x + xr1.x; l = fmaxf(v, NEG * v); p += l * av1.x;
            v = f2.y + xr1.y; l = fmaxf(v, NEG * v); p += l * av1.y;
            v = f3.x + xr1.z; l = fmaxf(v, NEG * v); p += l * av1.z;
            v = f3.y + xr1.w; l = fmaxf(v, NEG * v); p += l * av1.w;
        }
        p += __shfl_xor_sync(0xffffffffu, p, 1);
        p += __shfl_xor_sync(0xffffffffu, p, 2);
        p += __shfl_xor_sync(0xffffffffu, p, 4);

        float mn = fmaxf(m, p);
        float sc = __expf(m - mn);
        float w  = __expf(p - mn);
        s = s * sc + w;
        acc[0] = acc[0] * sc + w * f0.x;
        acc[1] = acc[1] * sc + w * f0.y;
        acc[2] = acc[2] * sc + w * f1.x;
        acc[3] = acc[3] * sc + w * f1.y;
        acc[4] = acc[4] * sc + w * f2.x;
        acc[5] = acc[5] * sc + w * f2.y;
        acc[6] = acc[6] * sc + w * f3.x;
        acc[7] = acc[7] * sc + w * f3.y;
        m = mn;
    }

    float inv = 1.f / s;
    float4 o0, o1;
    o0.x = fmaxf(acc[0] * inv + bias[coff + 0], 0.f);
    o0.y = fmaxf(acc[1] * inv + bias[coff + 1], 0.f);
    o0.z = fmaxf(acc[2] * inv + bias[coff + 2], 0.f);
    o0.w = fmaxf(acc[3] * inv + bias[coff + 3], 0.f);
    o1.x = fmaxf(acc[4] * inv + bias[coff + 4], 0.f);
    o1.y = fmaxf(acc[5] * inv + bias[coff + 5], 0.f);
    o1.z = fmaxf(acc[6] * inv + bias[coff + 6], 0.f);
    o1.w = fmaxf(acc[7] * inv + bias[coff + 7], 0.f);
    *(float4*)&g_h1[(size_t)n * D1 + coff]     = o0;
    *(float4*)&g_h1[(size_t)n * D1 + coff + 4] = o1;
}

// ---------------- GATv2 layer 2 (1 head, fp16 xl2) + fused mean-pool ----------------
__global__ __launch_bounds__(256) void edge2_kernel(
    const float* __restrict__ att, const float* __restrict__ bias,
    const int* __restrict__ batch)
{
    int n = blockIdx.x * 8 + (threadIdx.x >> 5);
    int lane = threadIdx.x & 31;
    int c = lane * 2;

    float2 av = *(const float2*)&att[c];
    float2 xr = *(const float2*)&g_xr2[(size_t)n * HID + c];

    int e0 = g_row[n], e1 = g_row[n + 1];
    float m = -3.4e38f, s = 0.f, a0 = 0.f, a1 = 0.f;

    const __half2* xlv = (const __half2*)g_xl2h;   // 2 halves per lane
    int src = g_src[e0];
    __half2 xh = xlv[(size_t)src * 32 + lane];

    for (int e = e0; e < e1; e++) {
        float2 b = __half22float2(xh);
        if (e + 1 < e1) {
            int ns = g_src[e + 1];
            xh = xlv[(size_t)ns * 32 + lane];
        }
        float v0 = b.x + xr.x; v0 = fmaxf(v0, NEG * v0);
        float v1 = b.y + xr.y; v1 = fmaxf(v1, NEG * v1);
        float p = v0 * av.x + v1 * av.y;
        #pragma unroll
        for (int off = 16; off; off >>= 1) p += __shfl_xor_sync(0xffffffffu, p, off);
        float mn = fmaxf(m, p);
        float sc = __expf(m - mn);
        float w  = __expf(p - mn);
        s  = s  * sc + w;
        a0 = a0 * sc + w * b.x;
        a1 = a1 * sc + w * b.y;
        m = mn;
    }
    float inv = 1.f / s;
    float o0 = a0 * inv + bias[c];
    float o1 = a1 * inv + bias[c + 1];

    int g = batch[n];
    atomicAdd(&g_pool[g * HID + c],     o0);
    atomicAdd(&g_pool[g * HID + c + 1], o1);
    if (lane == 0) atomicAdd(&g_cnt[g], 1.f);
}

// ---------------- MLP head: one block per graph ----------------
__global__ void head_kernel(const float* __restrict__ gf,
                            const float* __restrict__ w1, const float* __restrict__ b1,
                            const float* __restrict__ w2, const float* __restrict__ b2,
                            float* __restrict__ out)
{
    int g = blockIdx.x;
    int j = threadIdx.x;
    __shared__ float pl[HID];
    __shared__ float z[HID];

    float cm = fmaxf(g_cnt[g], 1.f);
    pl[j] = g_pool[g * HID + j] / cm;
    __syncthreads();

    float acc = b1[j];
    #pragma unroll 8
    for (int k = 0; k < HID; k++)   acc += pl[k] * w1[k * HID + j];
    #pragma unroll
    for (int k = 0; k < GFEAT; k++) acc += gf[g * GFEAT + k] * w1[(HID + k) * HID + j];
    z[j] = fmaxf(acc, 0.f);
    __syncthreads();

    if (j < NCLS) {
        float o = b2[j];
        #pragma unroll 8
        for (int k = 0; k < HID; k++) o += z[k] * w2[k * NCLS + j];
        out[g * NCLS + j] = o;
    }
}

// ---------------- launcher ----------------
extern "C" void kernel_launch(void* const* d_in, const int* in_sizes, int n_in,
                              void* d_out, int out_size)
{
    const float* x     = (const float*)d_in[0];
    const int*   ei    = (const int*)  d_in[1];
    const int*   batch = (const int*)  d_in[2];
    const float* gf    = (const float*)d_in[3];
    const float* W1l   = (const float*)d_in[4];
    const float* b1l   = (const float*)d_in[5];
    const float* W1r   = (const float*)d_in[6];
    const float* b1r   = (const float*)d_in[7];
    const float* att1  = (const float*)d_in[8];
    const float* bias1 = (const float*)d_in[9];
    const float* W2l   = (const float*)d_in[10];
    const float* b2l   = (const float*)d_in[11];
    const float* W2r   = (const float*)d_in[12];
    const float* b2r   = (const float*)d_in[13];
    const float* att2  = (const float*)d_in[14];
    const float* bias2 = (const float*)d_in[15];
    const float* l1W   = (const float*)d_in[16];
    const float* l1b   = (const float*)d_in[17];
    const float* l2W   = (const float*)d_in[18];
    const float* l2b   = (const float*)d_in[19];
    float* out = (float*)d_out;

    const int NBG = (NNODES + 127) / 128;     // 157
    const int NE4 = (ETOT + 1023) / 1024;     // blocks for 4-edge-per-thread kernels

    zero_kernel   <<<(NNODES + 255) / 256, 256>>>();
    count_kernel  <<<NE4, 256>>>(ei);
    scan_kernel   <<<1, 1024>>>();
    scatter_kernel<<<NE4, 256>>>(ei);

    gemm_tc_kernel<<<dim3(NBG, 8), 256>>>(1, x, W1l, b1l, W1r, b1r);
    edge1_kernel<<<NNODES / 4, 256>>>(att1, bias1);

    gemm_tc_kernel<<<dim3(NBG, 1), 256>>>(2, x, W2l, b2l, W2r, b2r);
    edge2_kernel<<<NNODES / 8, 256>>>(att2, bias2, batch);

    head_kernel<<<NGRAPH, HID>>>(gf, l1W, l1b, l2W, l2b, out);
}